// round 3
// baseline (speedup 1.0000x reference)
#include <cuda_runtime.h>
#include <cstdint>
#include <cstddef>

#define NWS   5000
#define NHRU  200000
#define NCH   50000
#define NGW   300000
#define CIN   16
#define HID   128
#define OUTD  64
#define TSTEPS 24
#define KH    144
#define NTOT  (NWS + NHRU)

__device__ __align__(256) float g_h[(size_t)NTOT * HID];
__device__ __align__(256) float g_Hws[(size_t)NWS * KH];
__device__ __align__(256) float g_Hhru[(size_t)NHRU * KH];
__device__ __align__(256) float g_Hch[(size_t)NCH * KH];
__device__ __align__(256) float g_Hgw[(size_t)NGW * KH];
__device__ __align__(256) float g_O1[(size_t)(NWS + NHRU + NCH + NGW) * HID];
__device__ __align__(256) float g_Y[(size_t)NGW * HID];
__device__ __align__(256) float g_inv[955000];
__device__ __align__(256) float g_wrs1[4 * KH * HID];
__device__ __align__(256) float g_bs1[4 * HID];
__device__ __align__(256) float g_wrs2[4 * HID * OUTD];
__device__ __align__(256) float g_bs2[4 * OUTD];
__device__ int g_is64;

typedef unsigned long long u64;

__device__ __forceinline__ u64 d_dup(float x) {
    u64 r; asm("mov.b64 %0,{%1,%1};" : "=l"(r) : "f"(x)); return r;
}
__device__ __forceinline__ void d_unpack(u64 v, float& x, float& y) {
    asm("mov.b64 {%0,%1},%2;" : "=f"(x), "=f"(y) : "l"(v));
}
__device__ __forceinline__ u64 d_fma2(u64 a, u64 b, u64 c) {
    u64 d; asm("fma.rn.f32x2 %0,%1,%2,%3;" : "=l"(d) : "l"(a), "l"(b), "l"(c)); return d;
}
__device__ __forceinline__ float d_sigm(float x) { return 1.f / (1.f + __expf(-x)); }

__global__ void detect_kernel(const int* __restrict__ p) {
    __shared__ int bad;
    if (threadIdx.x == 0) bad = 0;
    __syncthreads();
    for (int j = threadIdx.x; j < 2048; j += blockDim.x)
        if (p[2 * j + 1] != 0) bad = 1;
    __syncthreads();
    if (threadIdx.x == 0) g_is64 = (bad == 0);
}

__device__ __forceinline__ long long fetch_idx(const void* p, int i, int is64) {
    return is64 ? ((const long long*)p)[i] : (long long)((const int*)p)[i];
}

// ------------------- fused GRU step: 128 nodes/block, 256 thr -------------
__global__ __launch_bounds__(256, 1)
void gru_step_kernel(const float* __restrict__ ts_ws, const float* __restrict__ ts_hru,
                     const float* __restrict__ Wz, const float* __restrict__ Wr,
                     const float* __restrict__ Wh, const float* __restrict__ bz,
                     const float* __restrict__ br, const float* __restrict__ bh,
                     float* __restrict__ h_all, int t)
{
    extern __shared__ float sm[];
    float* sXH = sm;               // [128][KH]
    float* sRH = sm + 128 * KH;    // [128][HID]
    const int m0  = blockIdx.x * 128;
    const int tid = threadIdx.x;

    for (int idx = tid; idx < 128 * KH; idx += 256) {
        int m = idx / KH, k = idx - m * KH;
        int g = m0 + m;
        float v = 0.f;
        if (g < NTOT) {
            if (k < CIN)
                v = (g < NWS) ? ts_ws[(size_t)t * NWS * CIN + (size_t)g * CIN + k]
                              : ts_hru[(size_t)t * NHRU * CIN + (size_t)(g - NWS) * CIN + k];
            else
                v = h_all[(size_t)g * HID + (k - CIN)];
        }
        sXH[idx] = v;
    }
    __syncthreads();

    const int tx = tid & 15, ty = tid >> 4;
    const int colb = tx * 8, rowb = ty * 8;

    u64 az[8][4], ar[8][4];
    #pragma unroll
    for (int i = 0; i < 8; i++)
        #pragma unroll
        for (int j = 0; j < 4; j++) { az[i][j] = 0ull; ar[i][j] = 0ull; }

    for (int k = 0; k < KH; k++) {
        const u64* wzp = (const u64*)(Wz + (size_t)k * HID + colb);
        const u64* wrp = (const u64*)(Wr + (size_t)k * HID + colb);
        u64 wz[4], wr_[4];
        #pragma unroll
        for (int j = 0; j < 4; j++) { wz[j] = wzp[j]; wr_[j] = wrp[j]; }
        #pragma unroll
        for (int ii = 0; ii < 8; ii++) {
            u64 a2 = d_dup(sXH[(rowb + ii) * KH + k]);
            #pragma unroll
            for (int j = 0; j < 4; j++) {
                az[ii][j] = d_fma2(a2, wz[j],  az[ii][j]);
                ar[ii][j] = d_fma2(a2, wr_[j], ar[ii][j]);
            }
        }
    }

    float zf[8][8];
    #pragma unroll
    for (int ii = 0; ii < 8; ii++) {
        int row = rowb + ii;
        #pragma unroll
        for (int j = 0; j < 4; j++) {
            float z0, z1, r0, r1;
            d_unpack(az[ii][j], z0, z1);
            d_unpack(ar[ii][j], r0, r1);
            int c0 = colb + 2 * j;
            z0 = d_sigm(z0 + bz[c0]);     z1 = d_sigm(z1 + bz[c0 + 1]);
            r0 = d_sigm(r0 + br[c0]);     r1 = d_sigm(r1 + br[c0 + 1]);
            float h0 = sXH[row * KH + CIN + c0];
            float h1 = sXH[row * KH + CIN + c0 + 1];
            sRH[row * HID + c0]     = r0 * h0;
            sRH[row * HID + c0 + 1] = r1 * h1;
            zf[ii][2 * j] = z0; zf[ii][2 * j + 1] = z1;
        }
    }
    __syncthreads();

    u64 ah[8][4];
    #pragma unroll
    for (int i = 0; i < 8; i++)
        #pragma unroll
        for (int j = 0; j < 4; j++) ah[i][j] = 0ull;

    for (int k = 0; k < CIN; k++) {
        const u64* whp = (const u64*)(Wh + (size_t)k * HID + colb);
        u64 wh[4];
        #pragma unroll
        for (int j = 0; j < 4; j++) wh[j] = whp[j];
        #pragma unroll
        for (int ii = 0; ii < 8; ii++) {
            u64 a2 = d_dup(sXH[(rowb + ii) * KH + k]);
            #pragma unroll
            for (int j = 0; j < 4; j++) ah[ii][j] = d_fma2(a2, wh[j], ah[ii][j]);
        }
    }
    for (int k = 0; k < HID; k++) {
        const u64* whp = (const u64*)(Wh + (size_t)(k + CIN) * HID + colb);
        u64 wh[4];
        #pragma unroll
        for (int j = 0; j < 4; j++) wh[j] = whp[j];
        #pragma unroll
        for (int ii = 0; ii < 8; ii++) {
            u64 a2 = d_dup(sRH[(rowb + ii) * HID + k]);
            #pragma unroll
            for (int j = 0; j < 4; j++) ah[ii][j] = d_fma2(a2, wh[j], ah[ii][j]);
        }
    }

    #pragma unroll
    for (int ii = 0; ii < 8; ii++) {
        int row = rowb + ii;
        int g = m0 + row;
        if (g >= NTOT) continue;
        #pragma unroll
        for (int j = 0; j < 4; j++) {
            float c0v, c1v;
            d_unpack(ah[ii][j], c0v, c1v);
            int c0 = colb + 2 * j;
            float hc0 = tanhf(c0v + bh[c0]);
            float hc1 = tanhf(c1v + bh[c0 + 1]);
            float h0 = sXH[row * KH + CIN + c0];
            float h1 = sXH[row * KH + CIN + c0 + 1];
            float z0 = zf[ii][2 * j], z1 = zf[ii][2 * j + 1];
            h_all[(size_t)g * HID + c0]     = z0 * h0 + (1.f - z0) * hc0;
            h_all[(size_t)g * HID + c0 + 1] = z1 * h1 + (1.f - z1) * hc1;
        }
    }
}

// ------------------- generic tiled GEMM ------------------------------------
template<int K, int N, bool RELU>
__global__ __launch_bounds__(256, 1)
void gemm_kernel(const float* __restrict__ A, const float* __restrict__ W,
                 const float* __restrict__ bias, float* __restrict__ C, int M)
{
    extern __shared__ float sA[];
    const int m0  = blockIdx.x * 128;
    const int tid = threadIdx.x;

    for (int idx = tid; idx < 128 * K; idx += 256) {
        int m = idx / K, k = idx - m * K;
        int g = m0 + m;
        float v = 0.f;
        if (g < M) { v = A[(size_t)g * K + k]; if (RELU) v = fmaxf(v, 0.f); }
        sA[idx] = v;
    }
    __syncthreads();

    const int tx = tid & 15, ty = tid >> 4;
    constexpr int CPT = N / 16;
    constexpr int JC  = CPT / 2;
    const int colb = tx * CPT, rowb = ty * 8;

    u64 acc[8][JC];
    #pragma unroll
    for (int i = 0; i < 8; i++)
        #pragma unroll
        for (int j = 0; j < JC; j++) acc[i][j] = 0ull;

    for (int k = 0; k < K; k++) {
        const u64* wp = (const u64*)(W + (size_t)k * N + colb);
        u64 w[JC];
        #pragma unroll
        for (int j = 0; j < JC; j++) w[j] = wp[j];
        #pragma unroll
        for (int ii = 0; ii < 8; ii++) {
            u64 a2 = d_dup(sA[(rowb + ii) * K + k]);
            #pragma unroll
            for (int j = 0; j < JC; j++) acc[ii][j] = d_fma2(a2, w[j], acc[ii][j]);
        }
    }

    #pragma unroll
    for (int ii = 0; ii < 8; ii++) {
        int g = m0 + rowb + ii;
        if (g >= M) continue;
        #pragma unroll
        for (int j = 0; j < JC; j++) {
            float v0, v1;
            d_unpack(acc[ii][j], v0, v1);
            int c0 = colb + 2 * j;
            if (bias) { v0 += bias[c0]; v1 += bias[c0 + 1]; }
            C[(size_t)g * N + c0]     = v0;
            C[(size_t)g * N + c0 + 1] = v1;
        }
    }
}

__global__ void build_h_kernel(const float* __restrict__ x, const float* __restrict__ hsrc,
                               float* __restrict__ H, int n)
{
    long long idx = (long long)blockIdx.x * blockDim.x + threadIdx.x;
    long long total = (long long)n * KH;
    if (idx >= total) return;
    int m = (int)(idx / KH), k = (int)(idx - (long long)m * KH);
    float v;
    if (k < CIN) v = x[(size_t)m * CIN + k];
    else         v = hsrc ? hsrc[(size_t)m * HID + (k - CIN)] : 0.f;
    H[idx] = v;
}

__global__ void wrsum_kernel(const float* __restrict__ Wr, const float* __restrict__ b,
                             float* __restrict__ Ws, float* __restrict__ bs, int K, int N)
{
    const int nrel[4]    = {1, 1, 3, 2};
    const int rels[4][3] = {{5, 0, 0}, {0, 0, 0}, {2, 4, 6}, {1, 3, 0}};
    int idx = blockIdx.x * blockDim.x + threadIdx.x;
    int total = 4 * K * N;
    if (idx < total) {
        int type = idx / (K * N), off = idx - type * (K * N);
        float s = 0.f;
        for (int q = 0; q < nrel[type]; q++) s += Wr[(size_t)rels[type][q] * K * N + off];
        Ws[idx] = s;
    }
    if (idx < 4 * N) {
        int type = idx / N, off = idx - type * N;
        float s = 0.f;
        for (int q = 0; q < nrel[type]; q++) s += b[(size_t)rels[type][q] * N + off];
        bs[idx] = s;
    }
}

__global__ void count_kernel(const void* __restrict__ ed, float* __restrict__ cnt,
                             int E, int ndst)
{
    int e = blockIdx.x * blockDim.x + threadIdx.x;
    if (e >= E) return;
    long long d = fetch_idx(ed, e, g_is64);
    if (d >= 0 && d < ndst) atomicAdd(&cnt[d], 1.f);
}

__global__ void inv_kernel(float* __restrict__ c, int n)
{
    int i = blockIdx.x * blockDim.x + threadIdx.x;
    if (i < n) c[i] = 1.f / fmaxf(c[i], 1.f);
}

template<int NC>
__global__ void scatter_kernel(const float* __restrict__ Y, const void* __restrict__ es,
                               const void* __restrict__ ed, const float* __restrict__ inv,
                               float* __restrict__ O, int E, int ndst)
{
    const int G = NC / 4;
    long long gid = (long long)blockIdx.x * blockDim.x + threadIdx.x;
    int e = (int)(gid / G);
    if (e >= E) return;
    int lane = (int)(gid - (long long)e * G);
    int is64 = g_is64;
    long long d = fetch_idx(ed, e, is64);
    if (d < 0 || d >= ndst) return;
    long long s = fetch_idx(es, e, is64);
    float iv = inv[d];
    float4 y = *(const float4*)(Y + (size_t)s * NC + (size_t)lane * 4);
    float* o = O + (size_t)d * NC + (size_t)lane * 4;
    atomicAdd(o + 0, y.x * iv);
    atomicAdd(o + 1, y.y * iv);
    atomicAdd(o + 2, y.z * iv);
    atomicAdd(o + 3, y.w * iv);
}

static inline int cdiv(long long a, long long b) { return (int)((a + b - 1) / b); }

extern "C" void kernel_launch(void* const* d_in, const int* in_sizes, int n_in,
                              void* d_out, int out_size)
{
    const float* x_ws   = (const float*)d_in[0];
    const float* x_hru  = (const float*)d_in[1];
    const float* x_ch   = (const float*)d_in[2];
    const float* x_gw   = (const float*)d_in[3];
    const float* ts_ws  = (const float*)d_in[4];
    const float* ts_hru = (const float*)d_in[5];
    const float* Wz = (const float*)d_in[6];
    const float* Wr = (const float*)d_in[7];
    const float* Wh = (const float*)d_in[8];
    const float* bz = (const float*)d_in[9];
    const float* br = (const float*)d_in[10];
    const float* bh = (const float*)d_in[11];
    const float* W1l = (const float*)d_in[12];
    const float* b1l = (const float*)d_in[13];
    const float* W1r = (const float*)d_in[14];
    const float* W2l = (const float*)d_in[15];
    const float* b2l = (const float*)d_in[16];
    const float* W2r = (const float*)d_in[17];

    const void* es[7]; const void* ed[7]; int E[7];
    for (int r = 0; r < 7; r++) {
        es[r] = d_in[18 + 2 * r];
        ed[r] = d_in[19 + 2 * r];
        E[r]  = in_sizes[18 + 2 * r];
    }

    float *h, *Hws, *Hhru, *Hch, *Hgw, *O1, *Y, *inv, *wrs1, *bs1, *wrs2, *bs2;
    cudaGetSymbolAddress((void**)&h,    g_h);
    cudaGetSymbolAddress((void**)&Hws,  g_Hws);
    cudaGetSymbolAddress((void**)&Hhru, g_Hhru);
    cudaGetSymbolAddress((void**)&Hch,  g_Hch);
    cudaGetSymbolAddress((void**)&Hgw,  g_Hgw);
    cudaGetSymbolAddress((void**)&O1,   g_O1);
    cudaGetSymbolAddress((void**)&Y,    g_Y);
    cudaGetSymbolAddress((void**)&inv,  g_inv);
    cudaGetSymbolAddress((void**)&wrs1, g_wrs1);
    cudaGetSymbolAddress((void**)&bs1,  g_bs1);
    cudaGetSymbolAddress((void**)&wrs2, g_wrs2);
    cudaGetSymbolAddress((void**)&bs2,  g_bs2);

    const int GRU_SMEM = (128 * KH + 128 * HID) * 4;
    const int SM144    = 128 * KH * 4;
    const int SM128    = 128 * HID * 4;
    cudaFuncSetAttribute((const void*)gru_step_kernel,
                         cudaFuncAttributeMaxDynamicSharedMemorySize, GRU_SMEM);
    cudaFuncSetAttribute((const void*)gemm_kernel<KH, HID, false>,
                         cudaFuncAttributeMaxDynamicSharedMemorySize, SM144);
    cudaFuncSetAttribute((const void*)gemm_kernel<HID, OUTD, true>,
                         cudaFuncAttributeMaxDynamicSharedMemorySize, SM128);

    detect_kernel<<<1, 1024>>>((const int*)es[0]);
    cudaMemsetAsync(h,   0, sizeof(float) * (size_t)NTOT * HID, 0);
    cudaMemsetAsync(inv, 0, sizeof(float) * 955000, 0);

    const int dstn[7]   = {NHRU, NGW, NCH, NGW, NCH, NWS, NCH};
    const int invoff[7] = {0, 200000, 500000, 550000, 850000, 900000, 905000};
    const int srct[7]   = {0, 1, 1, 2, 2, 1, 3};
    const int dstt[7]   = {1, 3, 2, 3, 2, 0, 2};
    const int srcn[7]   = {NWS, NHRU, NHRU, NCH, NCH, NHRU, NGW};

    for (int r = 0; r < 7; r++)
        count_kernel<<<cdiv(E[r], 256), 256>>>(ed[r], inv + invoff[r], E[r], dstn[r]);
    inv_kernel<<<cdiv(955000, 256), 256>>>(inv, 955000);

    for (int t = 0; t < TSTEPS; t++)
        gru_step_kernel<<<cdiv(NTOT, 128), 256, GRU_SMEM>>>(
            ts_ws, ts_hru, Wz, Wr, Wh, bz, br, bh, h, t);

    build_h_kernel<<<cdiv((long long)NWS * KH, 256), 256>>>(x_ws, h, Hws, NWS);
    build_h_kernel<<<cdiv((long long)NHRU * KH, 256), 256>>>(x_hru, h + (size_t)NWS * HID, Hhru, NHRU);
    build_h_kernel<<<cdiv((long long)NCH * KH, 256), 256>>>(x_ch, (const float*)nullptr, Hch, NCH);
    build_h_kernel<<<cdiv((long long)NGW * KH, 256), 256>>>(x_gw, (const float*)nullptr, Hgw, NGW);

    wrsum_kernel<<<cdiv(4 * KH * HID, 256), 256>>>(W1l ? W1r : W1r, b1l, wrs1, bs1, KH, HID);
    wrsum_kernel<<<cdiv(4 * HID * OUTD, 256), 256>>>(W2r, b2l, wrs2, bs2, HID, OUTD);

    const float* Htype[4] = {Hws, Hhru, Hch, Hgw};
    const int    ntype[4] = {NWS, NHRU, NCH, NGW};
    const size_t o1off[4] = {0, (size_t)NWS * HID, (size_t)(NWS + NHRU) * HID,
                             (size_t)(NWS + NHRU + NCH) * HID};

    // ---- Layer 1: self terms (write), then edge scatter (atomic add) ----
    for (int tpe = 0; tpe < 4; tpe++)
        gemm_kernel<KH, HID, false><<<cdiv(ntype[tpe], 128), 256, SM144>>>(
            Htype[tpe], wrs1 + (size_t)tpe * KH * HID, bs1 + tpe * HID,
            O1 + o1off[tpe], ntype[tpe]);

    for (int r = 0; r < 7; r++) {
        gemm_kernel<KH, HID, false><<<cdiv(srcn[r], 128), 256, SM144>>>(
            Htype[srct[r]], W1l + (size_t)r * KH * HID, nullptr, Y, srcn[r]);
        scatter_kernel<HID><<<cdiv((long long)E[r] * (HID / 4), 256), 256>>>(
            Y, es[r], ed[r], inv + invoff[r], O1 + o1off[dstt[r]], E[r], dstn[r]);
    }

    // ---- Layer 2 (relu on load), writes straight into d_out ----
    float* out = (float*)d_out;
    const size_t o2off[4] = {0, (size_t)NWS * OUTD, (size_t)(NWS + NHRU) * OUTD,
                             (size_t)(NWS + NHRU + NCH) * OUTD};

    for (int tpe = 0; tpe < 4; tpe++)
        gemm_kernel<HID, OUTD, true><<<cdiv(ntype[tpe], 128), 256, SM128>>>(
            O1 + o1off[tpe], wrs2 + (size_t)tpe * HID * OUTD, bs2 + tpe * OUTD,
            out + o2off[tpe], ntype[tpe]);

    for (int r = 0; r < 7; r++) {
        gemm_kernel<HID, OUTD, true><<<cdiv(srcn[r], 128), 256, SM128>>>(
            O1 + o1off[srct[r]], W2l + (size_t)r * HID * OUTD, nullptr, Y, srcn[r]);
        scatter_kernel<OUTD><<<cdiv((long long)E[r] * (OUTD / 4), 256), 256>>>(
            Y, es[r], ed[r], inv + invoff[r], out + o2off[dstt[r]], E[r], dstn[r]);
    }
}

// round 4
// speedup vs baseline: 1.0369x; 1.0369x over previous
#include <cuda_runtime.h>
#include <cstdint>
#include <cstddef>

#define NWS   5000
#define NHRU  200000
#define NCH   50000
#define NGW   300000
#define CIN   16
#define HID   128
#define OUTD  64
#define TSTEPS 24
#define KH    144
#define NTOT  (NWS + NHRU)

__device__ __align__(256) float g_h[(size_t)NTOT * HID];
__device__ __align__(256) float g_Hws[(size_t)NWS * KH];
__device__ __align__(256) float g_Hhru[(size_t)NHRU * KH];
__device__ __align__(256) float g_Hch[(size_t)NCH * KH];
__device__ __align__(256) float g_Hgw[(size_t)NGW * KH];
__device__ __align__(256) float g_O1[(size_t)(NWS + NHRU + NCH + NGW) * HID];
__device__ __align__(256) float g_Y[(size_t)NGW * HID];
__device__ __align__(256) float g_inv[955000];
__device__ __align__(256) float g_wrs1[4 * KH * HID];
__device__ __align__(256) float g_bs1[4 * HID];
__device__ __align__(256) float g_wrs2[4 * HID * OUTD];
__device__ __align__(256) float g_bs2[4 * OUTD];
__device__ int g_is64;

typedef unsigned long long u64;

__device__ __forceinline__ u64 d_dup(float x) {
    u64 r; asm("mov.b64 %0,{%1,%1};" : "=l"(r) : "f"(x)); return r;
}
__device__ __forceinline__ void d_unpack(u64 v, float& x, float& y) {
    asm("mov.b64 {%0,%1},%2;" : "=f"(x), "=f"(y) : "l"(v));
}
__device__ __forceinline__ u64 d_fma2(u64 a, u64 b, u64 c) {
    u64 d; asm("fma.rn.f32x2 %0,%1,%2,%3;" : "=l"(d) : "l"(a), "l"(b), "l"(c)); return d;
}
__device__ __forceinline__ float d_sigm(float x) { return 1.f / (1.f + __expf(-x)); }

__global__ void detect_kernel(const int* __restrict__ p) {
    __shared__ int bad;
    if (threadIdx.x == 0) bad = 0;
    __syncthreads();
    for (int j = threadIdx.x; j < 2048; j += blockDim.x)
        if (p[2 * j + 1] != 0) bad = 1;
    __syncthreads();
    if (threadIdx.x == 0) g_is64 = (bad == 0);
}

__device__ __forceinline__ long long fetch_idx(const void* p, int i, int is64) {
    return is64 ? ((const long long*)p)[i] : (long long)((const int*)p)[i];
}

// ---------------------------------------------------------------------------
// Core inner product: acc[8][JC] += S[rows rowb..rowb+7, k] * W[wrow0+k, colb..]
// 2-row register double-buffered weight prefetch to hide L1/L2 latency.
// ---------------------------------------------------------------------------
template<int NK, int NCOLS, int JC>
__device__ __forceinline__ void mm_acc(const float* __restrict__ W, int wrow0,
                                       const float* __restrict__ S, int stride,
                                       int rowb, int colb, u64 (&acc)[8][JC])
{
    const u64* w0 = (const u64*)(W + (size_t)wrow0 * NCOLS + colb);
    const int step = NCOLS / 2;                 // u64 per weight row
    u64 wA[JC], wB[JC], nA[JC], nB[JC];
    #pragma unroll
    for (int j = 0; j < JC; j++) { wA[j] = w0[j]; wB[j] = w0[step + j]; }
    #pragma unroll 2
    for (int k = 0; k < NK; k += 2) {
        if (k + 2 < NK) {
            #pragma unroll
            for (int j = 0; j < JC; j++) {
                nA[j] = w0[(size_t)(k + 2) * step + j];
                nB[j] = w0[(size_t)(k + 3) * step + j];
            }
        }
        #pragma unroll
        for (int ii = 0; ii < 8; ii++) {
            u64 d0 = d_dup(S[(rowb + ii) * stride + k]);
            #pragma unroll
            for (int j = 0; j < JC; j++) acc[ii][j] = d_fma2(d0, wA[j], acc[ii][j]);
        }
        #pragma unroll
        for (int ii = 0; ii < 8; ii++) {
            u64 d1 = d_dup(S[(rowb + ii) * stride + k + 1]);
            #pragma unroll
            for (int j = 0; j < JC; j++) acc[ii][j] = d_fma2(d1, wB[j], acc[ii][j]);
        }
        #pragma unroll
        for (int j = 0; j < JC; j++) { wA[j] = nA[j]; wB[j] = nB[j]; }
    }
}

// ------------------- fused GRU step: 128 nodes/block, 256 thr ---------------
__global__ __launch_bounds__(256, 1)
void gru_step_kernel(const float* __restrict__ ts_ws, const float* __restrict__ ts_hru,
                     const float* __restrict__ Wz, const float* __restrict__ Wr,
                     const float* __restrict__ Wh, const float* __restrict__ bz,
                     const float* __restrict__ br, const float* __restrict__ bh,
                     float* __restrict__ h_all, int t)
{
    extern __shared__ float sm[];
    float* sXH = sm;                       // [128][KH]
    float* sRH = sm + 128 * KH;            // [128][HID]
    float* sZ  = sRH + 128 * HID;          // [128][HID]
    const int m0  = blockIdx.x * 128;
    const int tid = threadIdx.x;

    for (int idx = tid; idx < 128 * KH; idx += 256) {
        int m = idx / KH, k = idx - m * KH;
        int g = m0 + m;
        float v = 0.f;
        if (g < NTOT) {
            if (k < CIN)
                v = (g < NWS) ? ts_ws[(size_t)t * NWS * CIN + (size_t)g * CIN + k]
                              : ts_hru[(size_t)t * NHRU * CIN + (size_t)(g - NWS) * CIN + k];
            else
                v = h_all[(size_t)g * HID + (k - CIN)];
        }
        sXH[idx] = v;
    }
    __syncthreads();

    const int tx = tid & 15, ty = tid >> 4;
    const int colb = tx * 8, rowb = ty * 8;
    u64 acc[8][4];

    // ---- Z pass ----
    #pragma unroll
    for (int i = 0; i < 8; i++)
        #pragma unroll
        for (int j = 0; j < 4; j++) acc[i][j] = 0ull;
    mm_acc<KH, HID, 4>(Wz, 0, sXH, KH, rowb, colb, acc);
    #pragma unroll
    for (int ii = 0; ii < 8; ii++) {
        int row = rowb + ii;
        #pragma unroll
        for (int j = 0; j < 4; j++) {
            float v0, v1; d_unpack(acc[ii][j], v0, v1);
            int c0 = colb + 2 * j;
            sZ[row * HID + c0]     = d_sigm(v0 + bz[c0]);
            sZ[row * HID + c0 + 1] = d_sigm(v1 + bz[c0 + 1]);
        }
    }

    // ---- R pass (writes r*h) ----
    #pragma unroll
    for (int i = 0; i < 8; i++)
        #pragma unroll
        for (int j = 0; j < 4; j++) acc[i][j] = 0ull;
    mm_acc<KH, HID, 4>(Wr, 0, sXH, KH, rowb, colb, acc);
    #pragma unroll
    for (int ii = 0; ii < 8; ii++) {
        int row = rowb + ii;
        #pragma unroll
        for (int j = 0; j < 4; j++) {
            float v0, v1; d_unpack(acc[ii][j], v0, v1);
            int c0 = colb + 2 * j;
            float r0 = d_sigm(v0 + br[c0]);
            float r1 = d_sigm(v1 + br[c0 + 1]);
            sRH[row * HID + c0]     = r0 * sXH[row * KH + CIN + c0];
            sRH[row * HID + c0 + 1] = r1 * sXH[row * KH + CIN + c0 + 1];
        }
    }
    __syncthreads();

    // ---- H pass: Wh[0:16]·x + Wh[16:144]·(r*h) ----
    #pragma unroll
    for (int i = 0; i < 8; i++)
        #pragma unroll
        for (int j = 0; j < 4; j++) acc[i][j] = 0ull;
    mm_acc<CIN, HID, 4>(Wh, 0,   sXH, KH,  rowb, colb, acc);
    mm_acc<HID, HID, 4>(Wh, CIN, sRH, HID, rowb, colb, acc);

    #pragma unroll
    for (int ii = 0; ii < 8; ii++) {
        int row = rowb + ii;
        int g = m0 + row;
        if (g >= NTOT) continue;
        #pragma unroll
        for (int j = 0; j < 4; j++) {
            float v0, v1; d_unpack(acc[ii][j], v0, v1);
            int c0 = colb + 2 * j;
            float hc0 = tanhf(v0 + bh[c0]);
            float hc1 = tanhf(v1 + bh[c0 + 1]);
            float h0 = sXH[row * KH + CIN + c0];
            float h1 = sXH[row * KH + CIN + c0 + 1];
            float z0 = sZ[row * HID + c0];
            float z1 = sZ[row * HID + c0 + 1];
            h_all[(size_t)g * HID + c0]     = z0 * h0 + (1.f - z0) * hc0;
            h_all[(size_t)g * HID + c0 + 1] = z1 * h1 + (1.f - z1) * hc1;
        }
    }
}

// ------------------- generic tiled GEMM ------------------------------------
template<int K, int N, bool RELU>
__global__ __launch_bounds__(256, 1)
void gemm_kernel(const float* __restrict__ A, const float* __restrict__ W,
                 const float* __restrict__ bias, float* __restrict__ C, int M)
{
    extern __shared__ float sA[];
    const int m0  = blockIdx.x * 128;
    const int tid = threadIdx.x;

    for (int idx = tid; idx < 128 * K; idx += 256) {
        int m = idx / K, k = idx - m * K;
        int g = m0 + m;
        float v = 0.f;
        if (g < M) { v = A[(size_t)g * K + k]; if (RELU) v = fmaxf(v, 0.f); }
        sA[idx] = v;
    }
    __syncthreads();

    const int tx = tid & 15, ty = tid >> 4;
    constexpr int CPT = N / 16;
    constexpr int JC  = CPT / 2;
    const int colb = tx * CPT, rowb = ty * 8;

    u64 acc[8][JC];
    #pragma unroll
    for (int i = 0; i < 8; i++)
        #pragma unroll
        for (int j = 0; j < JC; j++) acc[i][j] = 0ull;

    mm_acc<K, N, JC>(W, 0, sA, K, rowb, colb, acc);

    #pragma unroll
    for (int ii = 0; ii < 8; ii++) {
        int g = m0 + rowb + ii;
        if (g >= M) continue;
        #pragma unroll
        for (int j = 0; j < JC; j++) {
            float v0, v1; d_unpack(acc[ii][j], v0, v1);
            int c0 = colb + 2 * j;
            if (bias) { v0 += bias[c0]; v1 += bias[c0 + 1]; }
            C[(size_t)g * N + c0]     = v0;
            C[(size_t)g * N + c0 + 1] = v1;
        }
    }
}

__global__ void build_h_kernel(const float* __restrict__ x, const float* __restrict__ hsrc,
                               float* __restrict__ H, int n)
{
    long long idx = (long long)blockIdx.x * blockDim.x + threadIdx.x;
    long long total = (long long)n * KH;
    if (idx >= total) return;
    int m = (int)(idx / KH), k = (int)(idx - (long long)m * KH);
    float v;
    if (k < CIN) v = x[(size_t)m * CIN + k];
    else         v = hsrc ? hsrc[(size_t)m * HID + (k - CIN)] : 0.f;
    H[idx] = v;
}

__global__ void wrsum_kernel(const float* __restrict__ Wr, const float* __restrict__ b,
                             float* __restrict__ Ws, float* __restrict__ bs, int K, int N)
{
    const int nrel[4]    = {1, 1, 3, 2};
    const int rels[4][3] = {{5, 0, 0}, {0, 0, 0}, {2, 4, 6}, {1, 3, 0}};
    int idx = blockIdx.x * blockDim.x + threadIdx.x;
    int total = 4 * K * N;
    if (idx < total) {
        int type = idx / (K * N), off = idx - type * (K * N);
        float s = 0.f;
        for (int q = 0; q < nrel[type]; q++) s += Wr[(size_t)rels[type][q] * K * N + off];
        Ws[idx] = s;
    }
    if (idx < 4 * N) {
        int type = idx / N, off = idx - type * N;
        float s = 0.f;
        for (int q = 0; q < nrel[type]; q++) s += b[(size_t)rels[type][q] * N + off];
        bs[idx] = s;
    }
}

__global__ void count_kernel(const void* __restrict__ ed, float* __restrict__ cnt,
                             int E, int ndst)
{
    int e = blockIdx.x * blockDim.x + threadIdx.x;
    if (e >= E) return;
    long long d = fetch_idx(ed, e, g_is64);
    if (d >= 0 && d < ndst) atomicAdd(&cnt[d], 1.f);
}

__global__ void inv_kernel(float* __restrict__ c, int n)
{
    int i = blockIdx.x * blockDim.x + threadIdx.x;
    if (i < n) c[i] = 1.f / fmaxf(c[i], 1.f);
}

template<int NC>
__global__ void scatter_kernel(const float* __restrict__ Y, const void* __restrict__ es,
                               const void* __restrict__ ed, const float* __restrict__ inv,
                               float* __restrict__ O, int E, int ndst)
{
    const int G = NC / 4;
    long long gid = (long long)blockIdx.x * blockDim.x + threadIdx.x;
    int e = (int)(gid / G);
    if (e >= E) return;
    int lane = (int)(gid - (long long)e * G);
    int is64 = g_is64;
    long long d = fetch_idx(ed, e, is64);
    if (d < 0 || d >= ndst) return;
    long long s = fetch_idx(es, e, is64);
    float iv = inv[d];
    float4 y = *(const float4*)(Y + (size_t)s * NC + (size_t)lane * 4);
    float* o = O + (size_t)d * NC + (size_t)lane * 4;
    atomicAdd(o + 0, y.x * iv);
    atomicAdd(o + 1, y.y * iv);
    atomicAdd(o + 2, y.z * iv);
    atomicAdd(o + 3, y.w * iv);
}

static inline int cdiv(long long a, long long b) { return (int)((a + b - 1) / b); }

extern "C" void kernel_launch(void* const* d_in, const int* in_sizes, int n_in,
                              void* d_out, int out_size)
{
    const float* x_ws   = (const float*)d_in[0];
    const float* x_hru  = (const float*)d_in[1];
    const float* x_ch   = (const float*)d_in[2];
    const float* x_gw   = (const float*)d_in[3];
    const float* ts_ws  = (const float*)d_in[4];
    const float* ts_hru = (const float*)d_in[5];
    const float* Wz = (const float*)d_in[6];
    const float* Wr = (const float*)d_in[7];
    const float* Wh = (const float*)d_in[8];
    const float* bz = (const float*)d_in[9];
    const float* br = (const float*)d_in[10];
    const float* bh = (const float*)d_in[11];
    const float* W1l = (const float*)d_in[12];
    const float* b1l = (const float*)d_in[13];
    const float* W1r = (const float*)d_in[14];
    const float* W2l = (const float*)d_in[15];
    const float* b2l = (const float*)d_in[16];
    const float* W2r = (const float*)d_in[17];

    const void* es[7]; const void* ed[7]; int E[7];
    for (int r = 0; r < 7; r++) {
        es[r] = d_in[18 + 2 * r];
        ed[r] = d_in[19 + 2 * r];
        E[r]  = in_sizes[18 + 2 * r];
    }

    float *h, *Hws, *Hhru, *Hch, *Hgw, *O1, *Y, *inv, *wrs1, *bs1, *wrs2, *bs2;
    cudaGetSymbolAddress((void**)&h,    g_h);
    cudaGetSymbolAddress((void**)&Hws,  g_Hws);
    cudaGetSymbolAddress((void**)&Hhru, g_Hhru);
    cudaGetSymbolAddress((void**)&Hch,  g_Hch);
    cudaGetSymbolAddress((void**)&Hgw,  g_Hgw);
    cudaGetSymbolAddress((void**)&O1,   g_O1);
    cudaGetSymbolAddress((void**)&Y,    g_Y);
    cudaGetSymbolAddress((void**)&inv,  g_inv);
    cudaGetSymbolAddress((void**)&wrs1, g_wrs1);
    cudaGetSymbolAddress((void**)&bs1,  g_bs1);
    cudaGetSymbolAddress((void**)&wrs2, g_wrs2);
    cudaGetSymbolAddress((void**)&bs2,  g_bs2);

    const int GRU_SMEM = (128 * KH + 2 * 128 * HID) * 4;   // 204800
    const int SM144    = 128 * KH * 4;
    const int SM128    = 128 * HID * 4;
    cudaFuncSetAttribute((const void*)gru_step_kernel,
                         cudaFuncAttributeMaxDynamicSharedMemorySize, GRU_SMEM);
    cudaFuncSetAttribute((const void*)gemm_kernel<KH, HID, false>,
                         cudaFuncAttributeMaxDynamicSharedMemorySize, SM144);
    cudaFuncSetAttribute((const void*)gemm_kernel<HID, OUTD, true>,
                         cudaFuncAttributeMaxDynamicSharedMemorySize, SM128);

    detect_kernel<<<1, 1024>>>((const int*)es[0]);
    cudaMemsetAsync(h,   0, sizeof(float) * (size_t)NTOT * HID, 0);
    cudaMemsetAsync(inv, 0, sizeof(float) * 955000, 0);

    const int dstn[7]   = {NHRU, NGW, NCH, NGW, NCH, NWS, NCH};
    const int invoff[7] = {0, 200000, 500000, 550000, 850000, 900000, 905000};
    const int srct[7]   = {0, 1, 1, 2, 2, 1, 3};
    const int dstt[7]   = {1, 3, 2, 3, 2, 0, 2};
    const int srcn[7]   = {NWS, NHRU, NHRU, NCH, NCH, NHRU, NGW};

    for (int r = 0; r < 7; r++)
        count_kernel<<<cdiv(E[r], 256), 256>>>(ed[r], inv + invoff[r], E[r], dstn[r]);
    inv_kernel<<<cdiv(955000, 256), 256>>>(inv, 955000);

    for (int t = 0; t < TSTEPS; t++)
        gru_step_kernel<<<cdiv(NTOT, 128), 256, GRU_SMEM>>>(
            ts_ws, ts_hru, Wz, Wr, Wh, bz, br, bh, h, t);

    build_h_kernel<<<cdiv((long long)NWS * KH, 256), 256>>>(x_ws, h, Hws, NWS);
    build_h_kernel<<<cdiv((long long)NHRU * KH, 256), 256>>>(x_hru, h + (size_t)NWS * HID, Hhru, NHRU);
    build_h_kernel<<<cdiv((long long)NCH * KH, 256), 256>>>(x_ch, (const float*)nullptr, Hch, NCH);
    build_h_kernel<<<cdiv((long long)NGW * KH, 256), 256>>>(x_gw, (const float*)nullptr, Hgw, NGW);

    wrsum_kernel<<<cdiv(4 * KH * HID, 256), 256>>>(W1r, b1l, wrs1, bs1, KH, HID);
    wrsum_kernel<<<cdiv(4 * HID * OUTD, 256), 256>>>(W2r, b2l, wrs2, bs2, HID, OUTD);

    const float* Htype[4] = {Hws, Hhru, Hch, Hgw};
    const int    ntype[4] = {NWS, NHRU, NCH, NGW};
    const size_t o1off[4] = {0, (size_t)NWS * HID, (size_t)(NWS + NHRU) * HID,
                             (size_t)(NWS + NHRU + NCH) * HID};

    for (int tpe = 0; tpe < 4; tpe++)
        gemm_kernel<KH, HID, false><<<cdiv(ntype[tpe], 128), 256, SM144>>>(
            Htype[tpe], wrs1 + (size_t)tpe * KH * HID, bs1 + tpe * HID,
            O1 + o1off[tpe], ntype[tpe]);

    for (int r = 0; r < 7; r++) {
        gemm_kernel<KH, HID, false><<<cdiv(srcn[r], 128), 256, SM144>>>(
            Htype[srct[r]], W1l + (size_t)r * KH * HID, nullptr, Y, srcn[r]);
        scatter_kernel<HID><<<cdiv((long long)E[r] * (HID / 4), 256), 256>>>(
            Y, es[r], ed[r], inv + invoff[r], O1 + o1off[dstt[r]], E[r], dstn[r]);
    }

    float* out = (float*)d_out;
    const size_t o2off[4] = {0, (size_t)NWS * OUTD, (size_t)(NWS + NHRU) * OUTD,
                             (size_t)(NWS + NHRU + NCH) * OUTD};

    for (int tpe = 0; tpe < 4; tpe++)
        gemm_kernel<HID, OUTD, true><<<cdiv(ntype[tpe], 128), 256, SM128>>>(
            O1 + o1off[tpe], wrs2 + (size_t)tpe * HID * OUTD, bs2 + tpe * OUTD,
            out + o2off[tpe], ntype[tpe]);

    for (int r = 0; r < 7; r++) {
        gemm_kernel<HID, OUTD, true><<<cdiv(srcn[r], 128), 256, SM128>>>(
            O1 + o1off[srct[r]], W2l + (size_t)r * HID * OUTD, nullptr, Y, srcn[r]);
        scatter_kernel<OUTD><<<cdiv((long long)E[r] * (OUTD / 4), 256), 256>>>(
            Y, es[r], ed[r], inv + invoff[r], out + o2off[dstt[r]], E[r], dstn[r]);
    }
}

// round 5
// speedup vs baseline: 1.2283x; 1.1846x over previous
#include <cuda_runtime.h>
#include <cstdint>
#include <cstddef>

#define NWS   5000
#define NHRU  200000
#define NCH   50000
#define NGW   300000
#define CIN   16
#define HID   128
#define OUTD  64
#define TSTEPS 24
#define KH    144
#define NTOT  (NWS + NHRU)

__device__ __align__(256) float g_h[(size_t)NTOT * HID];
__device__ __align__(256) float g_Hws[(size_t)NWS * KH];
__device__ __align__(256) float g_Hhru[(size_t)NHRU * KH];
__device__ __align__(256) float g_Hch[(size_t)NCH * KH];
__device__ __align__(256) float g_Hgw[(size_t)NGW * KH];
__device__ __align__(256) float g_O1[(size_t)(NWS + NHRU + NCH + NGW) * HID];
__device__ __align__(256) float g_Y[(size_t)NGW * HID];
__device__ __align__(256) float g_inv[955000];
__device__ __align__(256) float g_wrs1[4 * KH * HID];
__device__ __align__(256) float g_bs1[4 * HID];
__device__ __align__(256) float g_wrs2[4 * HID * OUTD];
__device__ __align__(256) float g_bs2[4 * OUTD];
__device__ int g_is64;

typedef unsigned long long u64;

__device__ __forceinline__ u64 d_dup(float x) {
    u64 r; asm("mov.b64 %0,{%1,%1};" : "=l"(r) : "f"(x)); return r;
}
__device__ __forceinline__ void d_unpack(u64 v, float& x, float& y) {
    asm("mov.b64 {%0,%1},%2;" : "=f"(x), "=f"(y) : "l"(v));
}
__device__ __forceinline__ u64 d_fma2(u64 a, u64 b, u64 c) {
    u64 d; asm("fma.rn.f32x2 %0,%1,%2,%3;" : "=l"(d) : "l"(a), "l"(b), "l"(c)); return d;
}
__device__ __forceinline__ float d_sigm(float x) { return 1.f / (1.f + __expf(-x)); }
__device__ __forceinline__ float d_tanh(float x) { return 1.f - 2.f / (__expf(2.f * x) + 1.f); }

__global__ void detect_kernel(const int* __restrict__ p) {
    __shared__ int bad;
    if (threadIdx.x == 0) bad = 0;
    __syncthreads();
    for (int j = threadIdx.x; j < 2048; j += blockDim.x)
        if (p[2 * j + 1] != 0) bad = 1;
    __syncthreads();
    if (threadIdx.x == 0) g_is64 = (bad == 0);
}

__device__ __forceinline__ long long fetch_idx(const void* p, int i, int is64) {
    return is64 ? ((const long long*)p)[i] : (long long)((const int*)p)[i];
}

// ---------------------------------------------------------------------------
// SMEM-weight inner product. Column mapping per thread: cols {tx*2 + j*32}+0/1
// (conflict-free LDS.64 across a warp's 16 tx lanes).
// ---------------------------------------------------------------------------
template<int NK>
__device__ __forceinline__ void mm_s(const float* __restrict__ sW,
                                     const float* __restrict__ S, int stride,
                                     int rowb, int tx2, u64 (&acc)[8][4])
{
    #pragma unroll 4
    for (int k = 0; k < NK; k++) {
        const float* wr = sW + k * HID;
        u64 w0 = *(const u64*)(wr + tx2);
        u64 w1 = *(const u64*)(wr + tx2 + 32);
        u64 w2 = *(const u64*)(wr + tx2 + 64);
        u64 w3 = *(const u64*)(wr + tx2 + 96);
        #pragma unroll
        for (int ii = 0; ii < 8; ii++) {
            u64 a = d_dup(S[(rowb + ii) * stride + k]);
            acc[ii][0] = d_fma2(a, w0, acc[ii][0]);
            acc[ii][1] = d_fma2(a, w1, acc[ii][1]);
            acc[ii][2] = d_fma2(a, w2, acc[ii][2]);
            acc[ii][3] = d_fma2(a, w3, acc[ii][3]);
        }
    }
}

__device__ __forceinline__ void ld_w(float* __restrict__ sW, const float* __restrict__ W,
                                     int n, int tid)
{
    for (int i = tid * 4; i < n; i += 256 * 4)
        *(float4*)(sW + i) = *(const float4*)(W + i);
}

// ------------------- fused GRU step: 128 nodes/block, 256 thr ---------------
__global__ __launch_bounds__(256, 1)
void gru_step_kernel(const float* __restrict__ ts_ws, const float* __restrict__ ts_hru,
                     const float* __restrict__ Wz, const float* __restrict__ Wr,
                     const float* __restrict__ Wh, const float* __restrict__ bz,
                     const float* __restrict__ br, const float* __restrict__ bh,
                     float* __restrict__ h_all, int t)
{
    extern __shared__ float sm[];
    float* sXH = sm;                   // [128][144]
    float* sW  = sm + 128 * KH;        // [144][128] (active weight matrix)
    float* sRH = sW + KH * HID;        // [128][128]
    const int m0  = blockIdx.x * 128;
    const int tid = threadIdx.x;

    // load node tile + Wr together
    for (int idx = tid; idx < 128 * KH; idx += 256) {
        int m = idx / KH, k = idx - m * KH;
        int g = m0 + m;
        float v = 0.f;
        if (g < NTOT) {
            if (k < CIN)
                v = (g < NWS) ? ts_ws[(size_t)t * NWS * CIN + (size_t)g * CIN + k]
                              : ts_hru[(size_t)t * NHRU * CIN + (size_t)(g - NWS) * CIN + k];
            else
                v = h_all[(size_t)g * HID + (k - CIN)];
        }
        sXH[idx] = v;
    }
    ld_w(sW, Wr, KH * HID, tid);
    __syncthreads();

    const int tx = tid & 15, ty = tid >> 4;
    const int tx2 = tx * 2, rowb = ty * 8;
    u64 acc[8][4];

    // ---- R pass: sRH = sigmoid(XH@Wr + br) * h ----
    #pragma unroll
    for (int i = 0; i < 8; i++)
        #pragma unroll
        for (int j = 0; j < 4; j++) acc[i][j] = 0ull;
    mm_s<KH>(sW, sXH, KH, rowb, tx2, acc);
    #pragma unroll
    for (int ii = 0; ii < 8; ii++) {
        int row = rowb + ii;
        #pragma unroll
        for (int j = 0; j < 4; j++) {
            float v0, v1; d_unpack(acc[ii][j], v0, v1);
            int c0 = tx2 + j * 32;
            float r0 = d_sigm(v0 + bz[0] * 0.f + br[c0]);
            float r1 = d_sigm(v1 + br[c0 + 1]);
            sRH[row * HID + c0]     = r0 * sXH[row * KH + CIN + c0];
            sRH[row * HID + c0 + 1] = r1 * sXH[row * KH + CIN + c0 + 1];
        }
    }
    __syncthreads();

    // ---- H pass: hc = tanh([x, r*h] @ Wh + bh) held in registers ----
    ld_w(sW, Wh, KH * HID, tid);
    __syncthreads();
    #pragma unroll
    for (int i = 0; i < 8; i++)
        #pragma unroll
        for (int j = 0; j < 4; j++) acc[i][j] = 0ull;
    mm_s<CIN>(sW,             sXH, KH,  rowb, tx2, acc);
    mm_s<HID>(sW + CIN * HID, sRH, HID, rowb, tx2, acc);

    float hc[8][8];
    #pragma unroll
    for (int ii = 0; ii < 8; ii++)
        #pragma unroll
        for (int j = 0; j < 4; j++) {
            float v0, v1; d_unpack(acc[ii][j], v0, v1);
            int c0 = tx2 + j * 32;
            hc[ii][2 * j]     = d_tanh(v0 + bh[c0]);
            hc[ii][2 * j + 1] = d_tanh(v1 + bh[c0 + 1]);
        }
    __syncthreads();

    // ---- Z pass + combine ----
    ld_w(sW, Wz, KH * HID, tid);
    __syncthreads();
    #pragma unroll
    for (int i = 0; i < 8; i++)
        #pragma unroll
        for (int j = 0; j < 4; j++) acc[i][j] = 0ull;
    mm_s<KH>(sW, sXH, KH, rowb, tx2, acc);

    #pragma unroll
    for (int ii = 0; ii < 8; ii++) {
        int row = rowb + ii;
        int g = m0 + row;
        if (g >= NTOT) continue;
        #pragma unroll
        for (int j = 0; j < 4; j++) {
            float v0, v1; d_unpack(acc[ii][j], v0, v1);
            int c0 = tx2 + j * 32;
            float z0 = d_sigm(v0 + bz[c0]);
            float z1 = d_sigm(v1 + bz[c0 + 1]);
            float h0 = sXH[row * KH + CIN + c0];
            float h1 = sXH[row * KH + CIN + c0 + 1];
            h_all[(size_t)g * HID + c0]     = z0 * h0 + (1.f - z0) * hc[ii][2 * j];
            h_all[(size_t)g * HID + c0 + 1] = z1 * h1 + (1.f - z1) * hc[ii][2 * j + 1];
        }
    }
}

// ------------------- generic tiled GEMM (global-weight prefetch) ------------
template<int NK, int NCOLS, int JC>
__device__ __forceinline__ void mm_acc(const float* __restrict__ W, int wrow0,
                                       const float* __restrict__ S, int stride,
                                       int rowb, int colb, u64 (&acc)[8][JC])
{
    const u64* w0 = (const u64*)(W + (size_t)wrow0 * NCOLS + colb);
    const int step = NCOLS / 2;
    u64 wA[JC], wB[JC], nA[JC], nB[JC];
    #pragma unroll
    for (int j = 0; j < JC; j++) { wA[j] = w0[j]; wB[j] = w0[step + j]; }
    #pragma unroll 2
    for (int k = 0; k < NK; k += 2) {
        if (k + 2 < NK) {
            #pragma unroll
            for (int j = 0; j < JC; j++) {
                nA[j] = w0[(size_t)(k + 2) * step + j];
                nB[j] = w0[(size_t)(k + 3) * step + j];
            }
        }
        #pragma unroll
        for (int ii = 0; ii < 8; ii++) {
            u64 d0 = d_dup(S[(rowb + ii) * stride + k]);
            #pragma unroll
            for (int j = 0; j < JC; j++) acc[ii][j] = d_fma2(d0, wA[j], acc[ii][j]);
        }
        #pragma unroll
        for (int ii = 0; ii < 8; ii++) {
            u64 d1 = d_dup(S[(rowb + ii) * stride + k + 1]);
            #pragma unroll
            for (int j = 0; j < JC; j++) acc[ii][j] = d_fma2(d1, wB[j], acc[ii][j]);
        }
        #pragma unroll
        for (int j = 0; j < JC; j++) { wA[j] = nA[j]; wB[j] = nB[j]; }
    }
}

template<int K, int N, bool RELU>
__global__ __launch_bounds__(256, 1)
void gemm_kernel(const float* __restrict__ A, const float* __restrict__ W,
                 const float* __restrict__ bias, float* __restrict__ C, int M)
{
    extern __shared__ float sA[];
    const int m0  = blockIdx.x * 128;
    const int tid = threadIdx.x;

    for (int idx = tid; idx < 128 * K; idx += 256) {
        int m = idx / K, k = idx - m * K;
        int g = m0 + m;
        float v = 0.f;
        if (g < M) { v = A[(size_t)g * K + k]; if (RELU) v = fmaxf(v, 0.f); }
        sA[idx] = v;
    }
    __syncthreads();

    const int tx = tid & 15, ty = tid >> 4;
    constexpr int CPT = N / 16;
    constexpr int JC  = CPT / 2;
    const int colb = tx * CPT, rowb = ty * 8;

    u64 acc[8][JC];
    #pragma unroll
    for (int i = 0; i < 8; i++)
        #pragma unroll
        for (int j = 0; j < JC; j++) acc[i][j] = 0ull;

    mm_acc<K, N, JC>(W, 0, sA, K, rowb, colb, acc);

    #pragma unroll
    for (int ii = 0; ii < 8; ii++) {
        int g = m0 + rowb + ii;
        if (g >= M) continue;
        #pragma unroll
        for (int j = 0; j < JC; j++) {
            float v0, v1; d_unpack(acc[ii][j], v0, v1);
            int c0 = colb + 2 * j;
            if (bias) { v0 += bias[c0]; v1 += bias[c0 + 1]; }
            C[(size_t)g * N + c0]     = v0;
            C[(size_t)g * N + c0 + 1] = v1;
        }
    }
}

__global__ void build_h_kernel(const float* __restrict__ x, const float* __restrict__ hsrc,
                               float* __restrict__ H, int n)
{
    long long idx = (long long)blockIdx.x * blockDim.x + threadIdx.x;
    long long total = (long long)n * KH;
    if (idx >= total) return;
    int m = (int)(idx / KH), k = (int)(idx - (long long)m * KH);
    float v;
    if (k < CIN) v = x[(size_t)m * CIN + k];
    else         v = hsrc ? hsrc[(size_t)m * HID + (k - CIN)] : 0.f;
    H[idx] = v;
}

__global__ void wrsum_kernel(const float* __restrict__ Wr, const float* __restrict__ b,
                             float* __restrict__ Ws, float* __restrict__ bs, int K, int N)
{
    const int nrel[4]    = {1, 1, 3, 2};
    const int rels[4][3] = {{5, 0, 0}, {0, 0, 0}, {2, 4, 6}, {1, 3, 0}};
    int idx = blockIdx.x * blockDim.x + threadIdx.x;
    int total = 4 * K * N;
    if (idx < total) {
        int type = idx / (K * N), off = idx - type * (K * N);
        float s = 0.f;
        for (int q = 0; q < nrel[type]; q++) s += Wr[(size_t)rels[type][q] * K * N + off];
        Ws[idx] = s;
    }
    if (idx < 4 * N) {
        int type = idx / N, off = idx - type * N;
        float s = 0.f;
        for (int q = 0; q < nrel[type]; q++) s += b[(size_t)rels[type][q] * N + off];
        bs[idx] = s;
    }
}

__global__ void count_kernel(const void* __restrict__ ed, float* __restrict__ cnt,
                             int E, int ndst)
{
    int e = blockIdx.x * blockDim.x + threadIdx.x;
    if (e >= E) return;
    long long d = fetch_idx(ed, e, g_is64);
    if (d >= 0 && d < ndst) atomicAdd(&cnt[d], 1.f);
}

__global__ void inv_kernel(float* __restrict__ c, int n)
{
    int i = blockIdx.x * blockDim.x + threadIdx.x;
    if (i < n) c[i] = 1.f / fmaxf(c[i], 1.f);
}

template<int NC>
__global__ void scatter_kernel(const float* __restrict__ Y, const void* __restrict__ es,
                               const void* __restrict__ ed, const float* __restrict__ inv,
                               float* __restrict__ O, int E, int ndst)
{
    const int G = NC / 4;
    long long gid = (long long)blockIdx.x * blockDim.x + threadIdx.x;
    int e = (int)(gid / G);
    if (e >= E) return;
    int lane = (int)(gid - (long long)e * G);
    int is64 = g_is64;
    long long d = fetch_idx(ed, e, is64);
    if (d < 0 || d >= ndst) return;
    long long s = fetch_idx(es, e, is64);
    float iv = inv[d];
    float4 y = *(const float4*)(Y + (size_t)s * NC + (size_t)lane * 4);
    float* o = O + (size_t)d * NC + (size_t)lane * 4;
    atomicAdd(o + 0, y.x * iv);
    atomicAdd(o + 1, y.y * iv);
    atomicAdd(o + 2, y.z * iv);
    atomicAdd(o + 3, y.w * iv);
}

static inline int cdiv(long long a, long long b) { return (int)((a + b - 1) / b); }

extern "C" void kernel_launch(void* const* d_in, const int* in_sizes, int n_in,
                              void* d_out, int out_size)
{
    const float* x_ws   = (const float*)d_in[0];
    const float* x_hru  = (const float*)d_in[1];
    const float* x_ch   = (const float*)d_in[2];
    const float* x_gw   = (const float*)d_in[3];
    const float* ts_ws  = (const float*)d_in[4];
    const float* ts_hru = (const float*)d_in[5];
    const float* Wz = (const float*)d_in[6];
    const float* Wr = (const float*)d_in[7];
    const float* Wh = (const float*)d_in[8];
    const float* bz = (const float*)d_in[9];
    const float* br = (const float*)d_in[10];
    const float* bh = (const float*)d_in[11];
    const float* W1l = (const float*)d_in[12];
    const float* b1l = (const float*)d_in[13];
    const float* W1r = (const float*)d_in[14];
    const float* W2l = (const float*)d_in[15];
    const float* b2l = (const float*)d_in[16];
    const float* W2r = (const float*)d_in[17];

    const void* es[7]; const void* ed[7]; int E[7];
    for (int r = 0; r < 7; r++) {
        es[r] = d_in[18 + 2 * r];
        ed[r] = d_in[19 + 2 * r];
        E[r]  = in_sizes[18 + 2 * r];
    }

    float *h, *Hws, *Hhru, *Hch, *Hgw, *O1, *Y, *inv, *wrs1, *bs1, *wrs2, *bs2;
    cudaGetSymbolAddress((void**)&h,    g_h);
    cudaGetSymbolAddress((void**)&Hws,  g_Hws);
    cudaGetSymbolAddress((void**)&Hhru, g_Hhru);
    cudaGetSymbolAddress((void**)&Hch,  g_Hch);
    cudaGetSymbolAddress((void**)&Hgw,  g_Hgw);
    cudaGetSymbolAddress((void**)&O1,   g_O1);
    cudaGetSymbolAddress((void**)&Y,    g_Y);
    cudaGetSymbolAddress((void**)&inv,  g_inv);
    cudaGetSymbolAddress((void**)&wrs1, g_wrs1);
    cudaGetSymbolAddress((void**)&bs1,  g_bs1);
    cudaGetSymbolAddress((void**)&wrs2, g_wrs2);
    cudaGetSymbolAddress((void**)&bs2,  g_bs2);

    const int GRU_SMEM = (128 * KH + KH * HID + 128 * HID) * 4;  // 212992
    const int SM144    = 128 * KH * 4;
    const int SM128    = 128 * HID * 4;
    cudaFuncSetAttribute((const void*)gru_step_kernel,
                         cudaFuncAttributeMaxDynamicSharedMemorySize, GRU_SMEM);
    cudaFuncSetAttribute((const void*)gemm_kernel<KH, HID, false>,
                         cudaFuncAttributeMaxDynamicSharedMemorySize, SM144);
    cudaFuncSetAttribute((const void*)gemm_kernel<HID, OUTD, true>,
                         cudaFuncAttributeMaxDynamicSharedMemorySize, SM128);

    // GRU first (after detect/memsets) so ncu -s 5 -c 1 profiles a GRU step.
    detect_kernel<<<1, 1024>>>((const int*)es[0]);
    cudaMemsetAsync(h,   0, sizeof(float) * (size_t)NTOT * HID, 0);
    cudaMemsetAsync(inv, 0, sizeof(float) * 955000, 0);

    for (int t = 0; t < TSTEPS; t++)
        gru_step_kernel<<<cdiv(NTOT, 128), 256, GRU_SMEM>>>(
            ts_ws, ts_hru, Wz, Wr, Wh, bz, br, bh, h, t);

    const int dstn[7]   = {NHRU, NGW, NCH, NGW, NCH, NWS, NCH};
    const int invoff[7] = {0, 200000, 500000, 550000, 850000, 900000, 905000};
    const int srct[7]   = {0, 1, 1, 2, 2, 1, 3};
    const int dstt[7]   = {1, 3, 2, 3, 2, 0, 2};
    const int srcn[7]   = {NWS, NHRU, NHRU, NCH, NCH, NHRU, NGW};

    for (int r = 0; r < 7; r++)
        count_kernel<<<cdiv(E[r], 256), 256>>>(ed[r], inv + invoff[r], E[r], dstn[r]);
    inv_kernel<<<cdiv(955000, 256), 256>>>(inv, 955000);

    build_h_kernel<<<cdiv((long long)NWS * KH, 256), 256>>>(x_ws, h, Hws, NWS);
    build_h_kernel<<<cdiv((long long)NHRU * KH, 256), 256>>>(x_hru, h + (size_t)NWS * HID, Hhru, NHRU);
    build_h_kernel<<<cdiv((long long)NCH * KH, 256), 256>>>(x_ch, (const float*)nullptr, Hch, NCH);
    build_h_kernel<<<cdiv((long long)NGW * KH, 256), 256>>>(x_gw, (const float*)nullptr, Hgw, NGW);

    wrsum_kernel<<<cdiv(4 * KH * HID, 256), 256>>>(W1r, b1l, wrs1, bs1, KH, HID);
    wrsum_kernel<<<cdiv(4 * HID * OUTD, 256), 256>>>(W2r, b2l, wrs2, bs2, HID, OUTD);

    const float* Htype[4] = {Hws, Hhru, Hch, Hgw};
    const int    ntype[4] = {NWS, NHRU, NCH, NGW};
    const size_t o1off[4] = {0, (size_t)NWS * HID, (size_t)(NWS + NHRU) * HID,
                             (size_t)(NWS + NHRU + NCH) * HID};

    for (int tpe = 0; tpe < 4; tpe++)
        gemm_kernel<KH, HID, false><<<cdiv(ntype[tpe], 128), 256, SM144>>>(
            Htype[tpe], wrs1 + (size_t)tpe * KH * HID, bs1 + tpe * HID,
            O1 + o1off[tpe], ntype[tpe]);

    for (int r = 0; r < 7; r++) {
        gemm_kernel<KH, HID, false><<<cdiv(srcn[r], 128), 256, SM144>>>(
            Htype[srct[r]], W1l + (size_t)r * KH * HID, nullptr, Y, srcn[r]);
        scatter_kernel<HID><<<cdiv((long long)E[r] * (HID / 4), 256), 256>>>(
            Y, es[r], ed[r], inv + invoff[r], O1 + o1off[dstt[r]], E[r], dstn[r]);
    }

    float* out = (float*)d_out;
    const size_t o2off[4] = {0, (size_t)NWS * OUTD, (size_t)(NWS + NHRU) * OUTD,
                             (size_t)(NWS + NHRU + NCH) * OUTD};

    for (int tpe = 0; tpe < 4; tpe++)
        gemm_kernel<HID, OUTD, true><<<cdiv(ntype[tpe], 128), 256, SM128>>>(
            O1 + o1off[tpe], wrs2 + (size_t)tpe * HID * OUTD, bs2 + tpe * OUTD,
            out + o2off[tpe], ntype[tpe]);

    for (int r = 0; r < 7; r++) {
        gemm_kernel<HID, OUTD, true><<<cdiv(srcn[r], 128), 256, SM128>>>(
            O1 + o1off[srct[r]], W2l + (size_t)r * HID * OUTD, nullptr, Y, srcn[r]);
        scatter_kernel<OUTD><<<cdiv((long long)E[r] * (OUTD / 4), 256), 256>>>(
            Y, es[r], ed[r], inv + invoff[r], out + o2off[dstt[r]], E[r], dstn[r]);
    }
}

// round 6
// speedup vs baseline: 1.6814x; 1.3690x over previous
#include <cuda_runtime.h>
#include <cstdint>
#include <cstddef>

#define NWS   5000
#define NHRU  200000
#define NCH   50000
#define NGW   300000
#define CIN   16
#define HID   128
#define OUTD  64
#define TSTEPS 24
#define KH    144
#define NTOT  (NWS + NHRU)

__device__ __align__(256) float g_h[(size_t)NTOT * HID];
__device__ __align__(256) float g_Hws[(size_t)NWS * KH];
__device__ __align__(256) float g_Hhru[(size_t)NHRU * KH];
__device__ __align__(256) float g_Hch[(size_t)NCH * KH];
__device__ __align__(256) float g_Hgw[(size_t)NGW * KH];
__device__ __align__(256) float g_O1[(size_t)(NWS + NHRU + NCH + NGW) * HID];
__device__ __align__(256) float g_Y[(size_t)NGW * HID];
__device__ __align__(256) float g_inv[955000];
__device__ __align__(256) float g_wrs1[4 * KH * HID];
__device__ __align__(256) float g_bs1[4 * HID];
__device__ __align__(256) float g_wrs2[4 * HID * OUTD];
__device__ __align__(256) float g_bs2[4 * OUTD];
__device__ int g_is64;

typedef unsigned long long u64;

__device__ __forceinline__ u64 d_dup(float x) {
    u64 r; asm("mov.b64 %0,{%1,%1};" : "=l"(r) : "f"(x)); return r;
}
__device__ __forceinline__ void d_unpack(u64 v, float& x, float& y) {
    asm("mov.b64 {%0,%1},%2;" : "=f"(x), "=f"(y) : "l"(v));
}
__device__ __forceinline__ u64 d_fma2(u64 a, u64 b, u64 c) {
    u64 d; asm("fma.rn.f32x2 %0,%1,%2,%3;" : "=l"(d) : "l"(a), "l"(b), "l"(c)); return d;
}
__device__ __forceinline__ float d_sigm(float x) { return 1.f / (1.f + __expf(-x)); }
__device__ __forceinline__ float d_tanh(float x) { return 1.f - 2.f / (__expf(2.f * x) + 1.f); }

__global__ void detect_kernel(const int* __restrict__ p) {
    __shared__ int bad;
    if (threadIdx.x == 0) bad = 0;
    __syncthreads();
    for (int j = threadIdx.x; j < 2048; j += blockDim.x)
        if (p[2 * j + 1] != 0) bad = 1;
    __syncthreads();
    if (threadIdx.x == 0) g_is64 = (bad == 0);
}

__device__ __forceinline__ long long fetch_idx(const void* p, int i, int is64) {
    return is64 ? ((const long long*)p)[i] : (long long)((const int*)p)[i];
}

// ---------------------------------------------------------------------------
// SMEM-weight inner product, 4 rows/thread. Cols per thread: {tx*2 + j*32}+0/1
// ---------------------------------------------------------------------------
template<int NK>
__device__ __forceinline__ void mm_s(const float* __restrict__ sW,
                                     const float* __restrict__ S, int stride,
                                     int rowb, int tx2, u64 (&acc)[4][4])
{
    #pragma unroll 4
    for (int k = 0; k < NK; k++) {
        const float* wr = sW + k * HID;
        u64 w0 = *(const u64*)(wr + tx2);
        u64 w1 = *(const u64*)(wr + tx2 + 32);
        u64 w2 = *(const u64*)(wr + tx2 + 64);
        u64 w3 = *(const u64*)(wr + tx2 + 96);
        #pragma unroll
        for (int ii = 0; ii < 4; ii++) {
            u64 a = d_dup(S[(rowb + ii) * stride + k]);
            acc[ii][0] = d_fma2(a, w0, acc[ii][0]);
            acc[ii][1] = d_fma2(a, w1, acc[ii][1]);
            acc[ii][2] = d_fma2(a, w2, acc[ii][2]);
            acc[ii][3] = d_fma2(a, w3, acc[ii][3]);
        }
    }
}

__device__ __forceinline__ void ld_w(float* __restrict__ sW, const float* __restrict__ W,
                                     int n, int tid, int nthr)
{
    for (int i = tid * 4; i < n; i += nthr * 4)
        *(float4*)(sW + i) = *(const float4*)(W + i);
}

// ------------------- fused GRU step: 128 nodes/block, 512 thr ---------------
__global__ __launch_bounds__(512, 1)
void gru_step_kernel(const float* __restrict__ ts_ws, const float* __restrict__ ts_hru,
                     const float* __restrict__ Wz, const float* __restrict__ Wr,
                     const float* __restrict__ Wh, const float* __restrict__ bz,
                     const float* __restrict__ br, const float* __restrict__ bh,
                     float* __restrict__ h_all, int t)
{
    extern __shared__ float sm[];
    float* sXH = sm;                   // [128][144]
    float* sW  = sm + 128 * KH;        // [144][128]
    float* sRH = sW + KH * HID;        // [128][128]
    const int m0  = blockIdx.x * 128;
    const int tid = threadIdx.x;

    for (int idx = tid; idx < 128 * KH; idx += 512) {
        int m = idx / KH, k = idx - m * KH;
        int g = m0 + m;
        float v = 0.f;
        if (g < NTOT) {
            if (k < CIN)
                v = (g < NWS) ? ts_ws[(size_t)t * NWS * CIN + (size_t)g * CIN + k]
                              : ts_hru[(size_t)t * NHRU * CIN + (size_t)(g - NWS) * CIN + k];
            else
                v = h_all[(size_t)g * HID + (k - CIN)];
        }
        sXH[idx] = v;
    }
    ld_w(sW, Wr, KH * HID, tid, 512);
    __syncthreads();

    const int tx = tid & 15, ty = tid >> 4;      // ty in 0..31
    const int tx2 = tx * 2, rowb = ty * 4;
    u64 acc[4][4];

    // ---- R pass ----
    #pragma unroll
    for (int i = 0; i < 4; i++)
        #pragma unroll
        for (int j = 0; j < 4; j++) acc[i][j] = 0ull;
    mm_s<KH>(sW, sXH, KH, rowb, tx2, acc);
    #pragma unroll
    for (int ii = 0; ii < 4; ii++) {
        int row = rowb + ii;
        #pragma unroll
        for (int j = 0; j < 4; j++) {
            float v0, v1; d_unpack(acc[ii][j], v0, v1);
            int c0 = tx2 + j * 32;
            float r0 = d_sigm(v0 + br[c0]);
            float r1 = d_sigm(v1 + br[c0 + 1]);
            sRH[row * HID + c0]     = r0 * sXH[row * KH + CIN + c0];
            sRH[row * HID + c0 + 1] = r1 * sXH[row * KH + CIN + c0 + 1];
        }
    }
    __syncthreads();

    // ---- H pass ----
    ld_w(sW, Wh, KH * HID, tid, 512);
    __syncthreads();
    #pragma unroll
    for (int i = 0; i < 4; i++)
        #pragma unroll
        for (int j = 0; j < 4; j++) acc[i][j] = 0ull;
    mm_s<CIN>(sW,             sXH, KH,  rowb, tx2, acc);
    mm_s<HID>(sW + CIN * HID, sRH, HID, rowb, tx2, acc);

    float hc[4][8];
    #pragma unroll
    for (int ii = 0; ii < 4; ii++)
        #pragma unroll
        for (int j = 0; j < 4; j++) {
            float v0, v1; d_unpack(acc[ii][j], v0, v1);
            int c0 = tx2 + j * 32;
            hc[ii][2 * j]     = d_tanh(v0 + bh[c0]);
            hc[ii][2 * j + 1] = d_tanh(v1 + bh[c0 + 1]);
        }
    __syncthreads();

    // ---- Z pass + combine ----
    ld_w(sW, Wz, KH * HID, tid, 512);
    __syncthreads();
    #pragma unroll
    for (int i = 0; i < 4; i++)
        #pragma unroll
        for (int j = 0; j < 4; j++) acc[i][j] = 0ull;
    mm_s<KH>(sW, sXH, KH, rowb, tx2, acc);

    #pragma unroll
    for (int ii = 0; ii < 4; ii++) {
        int row = rowb + ii;
        int g = m0 + row;
        if (g >= NTOT) continue;
        #pragma unroll
        for (int j = 0; j < 4; j++) {
            float v0, v1; d_unpack(acc[ii][j], v0, v1);
            int c0 = tx2 + j * 32;
            float z0 = d_sigm(v0 + bz[c0]);
            float z1 = d_sigm(v1 + bz[c0 + 1]);
            float h0 = sXH[row * KH + CIN + c0];
            float h1 = sXH[row * KH + CIN + c0 + 1];
            h_all[(size_t)g * HID + c0]     = z0 * h0 + (1.f - z0) * hc[ii][2 * j];
            h_all[(size_t)g * HID + c0 + 1] = z1 * h1 + (1.f - z1) * hc[ii][2 * j + 1];
        }
    }
}

// ------------------- tiled GEMM: 128 rows, 512 thr, smem weights ------------
template<int K, int N, bool RELU>
__global__ __launch_bounds__(512, 1)
void gemm_kernel(const float* __restrict__ A, const float* __restrict__ W,
                 const float* __restrict__ bias, float* __restrict__ C, int M)
{
    extern __shared__ float sm[];
    float* sA = sm;                 // [128][K]
    float* sW = sm + 128 * K;       // [K][N]
    const int m0  = blockIdx.x * 128;
    const int tid = threadIdx.x;

    for (int idx = tid; idx < 128 * K; idx += 512) {
        int m = idx / K, k = idx - m * K;
        int g = m0 + m;
        float v = 0.f;
        if (g < M) { v = A[(size_t)g * K + k]; if (RELU) v = fmaxf(v, 0.f); }
        sA[idx] = v;
    }
    ld_w(sW, W, K * N, tid, 512);
    __syncthreads();

    const int tx = tid & 15, ty = tid >> 4;
    constexpr int JC = N / 32;           // u64 accs per row: 4 (N=128), 2 (N=64)
    const int tx2 = tx * 2, rowb = ty * 4;

    u64 acc[4][JC];
    #pragma unroll
    for (int i = 0; i < 4; i++)
        #pragma unroll
        for (int j = 0; j < JC; j++) acc[i][j] = 0ull;

    #pragma unroll 4
    for (int k = 0; k < K; k++) {
        const float* wr = sW + k * N;
        u64 w[JC];
        #pragma unroll
        for (int j = 0; j < JC; j++) w[j] = *(const u64*)(wr + tx2 + j * 32);
        #pragma unroll
        for (int ii = 0; ii < 4; ii++) {
            u64 a = d_dup(sA[(rowb + ii) * K + k]);
            #pragma unroll
            for (int j = 0; j < JC; j++) acc[ii][j] = d_fma2(a, w[j], acc[ii][j]);
        }
    }

    #pragma unroll
    for (int ii = 0; ii < 4; ii++) {
        int g = m0 + rowb + ii;
        if (g >= M) continue;
        #pragma unroll
        for (int j = 0; j < JC; j++) {
            float v0, v1; d_unpack(acc[ii][j], v0, v1);
            int c0 = tx2 + j * 32;
            if (bias) { v0 += bias[c0]; v1 += bias[c0 + 1]; }
            C[(size_t)g * N + c0]     = v0;
            C[(size_t)g * N + c0 + 1] = v1;
        }
    }
}

__global__ void build_h_kernel(const float* __restrict__ x, const float* __restrict__ hsrc,
                               float* __restrict__ H, int n)
{
    long long idx = (long long)blockIdx.x * blockDim.x + threadIdx.x;
    long long total = (long long)n * KH;
    if (idx >= total) return;
    int m = (int)(idx / KH), k = (int)(idx - (long long)m * KH);
    float v;
    if (k < CIN) v = x[(size_t)m * CIN + k];
    else         v = hsrc ? hsrc[(size_t)m * HID + (k - CIN)] : 0.f;
    H[idx] = v;
}

__global__ void wrsum_kernel(const float* __restrict__ Wr, const float* __restrict__ b,
                             float* __restrict__ Ws, float* __restrict__ bs, int K, int N)
{
    const int nrel[4]    = {1, 1, 3, 2};
    const int rels[4][3] = {{5, 0, 0}, {0, 0, 0}, {2, 4, 6}, {1, 3, 0}};
    int idx = blockIdx.x * blockDim.x + threadIdx.x;
    int total = 4 * K * N;
    if (idx < total) {
        int type = idx / (K * N), off = idx - type * (K * N);
        float s = 0.f;
        for (int q = 0; q < nrel[type]; q++) s += Wr[(size_t)rels[type][q] * K * N + off];
        Ws[idx] = s;
    }
    if (idx < 4 * N) {
        int type = idx / N, off = idx - type * N;
        float s = 0.f;
        for (int q = 0; q < nrel[type]; q++) s += b[(size_t)rels[type][q] * N + off];
        bs[idx] = s;
    }
}

__global__ void count_kernel(const void* __restrict__ ed, float* __restrict__ cnt,
                             int E, int ndst)
{
    int e = blockIdx.x * blockDim.x + threadIdx.x;
    if (e >= E) return;
    long long d = fetch_idx(ed, e, g_is64);
    if (d >= 0 && d < ndst) atomicAdd(&cnt[d], 1.f);
}

__global__ void inv_kernel(float* __restrict__ c, int n)
{
    int i = blockIdx.x * blockDim.x + threadIdx.x;
    if (i < n) c[i] = 1.f / fmaxf(c[i], 1.f);
}

template<int NC>
__global__ void scatter_kernel(const float* __restrict__ Y, const void* __restrict__ es,
                               const void* __restrict__ ed, const float* __restrict__ inv,
                               float* __restrict__ O, int E, int ndst)
{
    const int G = NC / 4;
    long long gid = (long long)blockIdx.x * blockDim.x + threadIdx.x;
    int e = (int)(gid / G);
    if (e >= E) return;
    int lane = (int)(gid - (long long)e * G);
    int is64 = g_is64;
    long long d = fetch_idx(ed, e, is64);
    if (d < 0 || d >= ndst) return;
    long long s = fetch_idx(es, e, is64);
    float iv = inv[d];
    float4 y = *(const float4*)(Y + (size_t)s * NC + (size_t)lane * 4);
    float* o = O + (size_t)d * NC + (size_t)lane * 4;
    atomicAdd(o + 0, y.x * iv);
    atomicAdd(o + 1, y.y * iv);
    atomicAdd(o + 2, y.z * iv);
    atomicAdd(o + 3, y.w * iv);
}

static inline int cdiv(long long a, long long b) { return (int)((a + b - 1) / b); }

extern "C" void kernel_launch(void* const* d_in, const int* in_sizes, int n_in,
                              void* d_out, int out_size)
{
    const float* x_ws   = (const float*)d_in[0];
    const float* x_hru  = (const float*)d_in[1];
    const float* x_ch   = (const float*)d_in[2];
    const float* x_gw   = (const float*)d_in[3];
    const float* ts_ws  = (const float*)d_in[4];
    const float* ts_hru = (const float*)d_in[5];
    const float* Wz = (const float*)d_in[6];
    const float* Wr = (const float*)d_in[7];
    const float* Wh = (const float*)d_in[8];
    const float* bz = (const float*)d_in[9];
    const float* br = (const float*)d_in[10];
    const float* bh = (const float*)d_in[11];
    const float* W1l = (const float*)d_in[12];
    const float* b1l = (const float*)d_in[13];
    const float* W1r = (const float*)d_in[14];
    const float* W2l = (const float*)d_in[15];
    const float* b2l = (const float*)d_in[16];
    const float* W2r = (const float*)d_in[17];

    const void* es[7]; const void* ed[7]; int E[7];
    for (int r = 0; r < 7; r++) {
        es[r] = d_in[18 + 2 * r];
        ed[r] = d_in[19 + 2 * r];
        E[r]  = in_sizes[18 + 2 * r];
    }

    float *h, *Hws, *Hhru, *Hch, *Hgw, *O1, *Y, *inv, *wrs1, *bs1, *wrs2, *bs2;
    cudaGetSymbolAddress((void**)&h,    g_h);
    cudaGetSymbolAddress((void**)&Hws,  g_Hws);
    cudaGetSymbolAddress((void**)&Hhru, g_Hhru);
    cudaGetSymbolAddress((void**)&Hch,  g_Hch);
    cudaGetSymbolAddress((void**)&Hgw,  g_Hgw);
    cudaGetSymbolAddress((void**)&O1,   g_O1);
    cudaGetSymbolAddress((void**)&Y,    g_Y);
    cudaGetSymbolAddress((void**)&inv,  g_inv);
    cudaGetSymbolAddress((void**)&wrs1, g_wrs1);
    cudaGetSymbolAddress((void**)&bs1,  g_bs1);
    cudaGetSymbolAddress((void**)&wrs2, g_wrs2);
    cudaGetSymbolAddress((void**)&bs2,  g_bs2);

    const int GRU_SMEM = (128 * KH + KH * HID + 128 * HID) * 4;  // 212992
    const int SM1 = (128 * KH + KH * HID) * 4;                    // 147456
    const int SM2 = (128 * HID + HID * OUTD) * 4;                 // 98304
    cudaFuncSetAttribute((const void*)gru_step_kernel,
                         cudaFuncAttributeMaxDynamicSharedMemorySize, GRU_SMEM);
    cudaFuncSetAttribute((const void*)gemm_kernel<KH, HID, false>,
                         cudaFuncAttributeMaxDynamicSharedMemorySize, SM1);
    cudaFuncSetAttribute((const void*)gemm_kernel<HID, OUTD, true>,
                         cudaFuncAttributeMaxDynamicSharedMemorySize, SM2);

    detect_kernel<<<1, 1024>>>((const int*)es[0]);
    cudaMemsetAsync(h,   0, sizeof(float) * (size_t)NTOT * HID, 0);
    cudaMemsetAsync(inv, 0, sizeof(float) * 955000, 0);

    for (int t = 0; t < TSTEPS; t++)
        gru_step_kernel<<<cdiv(NTOT, 128), 512, GRU_SMEM>>>(
            ts_ws, ts_hru, Wz, Wr, Wh, bz, br, bh, h, t);

    const int dstn[7]   = {NHRU, NGW, NCH, NGW, NCH, NWS, NCH};
    const int invoff[7] = {0, 200000, 500000, 550000, 850000, 900000, 905000};
    const int srct[7]   = {0, 1, 1, 2, 2, 1, 3};
    const int dstt[7]   = {1, 3, 2, 3, 2, 0, 2};
    const int srcn[7]   = {NWS, NHRU, NHRU, NCH, NCH, NHRU, NGW};

    for (int r = 0; r < 7; r++)
        count_kernel<<<cdiv(E[r], 256), 256>>>(ed[r], inv + invoff[r], E[r], dstn[r]);
    inv_kernel<<<cdiv(955000, 256), 256>>>(inv, 955000);

    build_h_kernel<<<cdiv((long long)NWS * KH, 256), 256>>>(x_ws, h, Hws, NWS);
    build_h_kernel<<<cdiv((long long)NHRU * KH, 256), 256>>>(x_hru, h + (size_t)NWS * HID, Hhru, NHRU);
    build_h_kernel<<<cdiv((long long)NCH * KH, 256), 256>>>(x_ch, (const float*)nullptr, Hch, NCH);
    build_h_kernel<<<cdiv((long long)NGW * KH, 256), 256>>>(x_gw, (const float*)nullptr, Hgw, NGW);

    wrsum_kernel<<<cdiv(4 * KH * HID, 256), 256>>>(W1r, b1l, wrs1, bs1, KH, HID);
    wrsum_kernel<<<cdiv(4 * HID * OUTD, 256), 256>>>(W2r, b2l, wrs2, bs2, HID, OUTD);

    const float* Htype[4] = {Hws, Hhru, Hch, Hgw};
    const int    ntype[4] = {NWS, NHRU, NCH, NGW};
    const size_t o1off[4] = {0, (size_t)NWS * HID, (size_t)(NWS + NHRU) * HID,
                             (size_t)(NWS + NHRU + NCH) * HID};

    for (int tpe = 0; tpe < 4; tpe++)
        gemm_kernel<KH, HID, false><<<cdiv(ntype[tpe], 128), 512, SM1>>>(
            Htype[tpe], wrs1 + (size_t)tpe * KH * HID, bs1 + tpe * HID,
            O1 + o1off[tpe], ntype[tpe]);

    for (int r = 0; r < 7; r++) {
        gemm_kernel<KH, HID, false><<<cdiv(srcn[r], 128), 512, SM1>>>(
            Htype[srct[r]], W1l + (size_t)r * KH * HID, nullptr, Y, srcn[r]);
        scatter_kernel<HID><<<cdiv((long long)E[r] * (HID / 4), 256), 256>>>(
            Y, es[r], ed[r], inv + invoff[r], O1 + o1off[dstt[r]], E[r], dstn[r]);
    }

    float* out = (float*)d_out;
    const size_t o2off[4] = {0, (size_t)NWS * OUTD, (size_t)(NWS + NHRU) * OUTD,
                             (size_t)(NWS + NHRU + NCH) * OUTD};

    for (int tpe = 0; tpe < 4; tpe++)
        gemm_kernel<HID, OUTD, true><<<cdiv(ntype[tpe], 128), 512, SM2>>>(
            O1 + o1off[tpe], wrs2 + (size_t)tpe * HID * OUTD, bs2 + tpe * OUTD,
            out + o2off[tpe], ntype[tpe]);

    for (int r = 0; r < 7; r++) {
        gemm_kernel<HID, OUTD, true><<<cdiv(srcn[r], 128), 512, SM2>>>(
            O1 + o1off[srct[r]], W2l + (size_t)r * HID * OUTD, nullptr, Y, srcn[r]);
        scatter_kernel<OUTD><<<cdiv((long long)E[r] * (OUTD / 4), 256), 256>>>(
            Y, es[r], ed[r], inv + invoff[r], out + o2off[dstt[r]], E[r], dstn[r]);
    }
}